// round 8
// baseline (speedup 1.0000x reference)
#include <cuda_runtime.h>
#include <cuda_bf16.h>
#include <stdint.h>
#include <math.h>

#define ZB   16
#define ZD   256
#define ZT   4096
#define NVEC (ZB*ZT)            // 65536
#define NELEM (ZB*ZD*ZT)        // 16777216
#define NCODE 1024

#define TILE_M 128
#define TILE_N 128
#define BK     32
#define NT_TILES (NCODE/TILE_N)   // 8
#define KCH      (ZD/BK)          // 8
#define NITER    (NT_TILES*KCH)   // 64

// A row stride: 264 bf16 = 528 B (conflict-free fragment loads)
#define STRA_E 264
#define STRA_B (STRA_E*2)
#define A_H_OFF 0
// B (hi only): 128 rows x 80B, double buffered
#define STRB_B 80
#define B_HL   (TILE_N*STRB_B)             // 10240
#define B_BASE (TILE_M*STRA_B)             // 67584
#define SZH    (B_BASE + 2*B_HL)           // 88064
#define SZL    (SZH + 512)                 // 88576
#define STD    (SZL + 512)                 // 89088 [row][wn][3] floats
#define STI    (STD + TILE_M*4*3*4)        // 95232
#define SMEM_TOTAL (STI + TILE_M*4*3*4)    // 101376

// ---------------- scratch --------------------------------------------------
__device__ __align__(16) __nv_bfloat16 g_eh[NCODE*ZD];
__device__ __align__(16) float g_zt[(size_t)NVEC*ZD];   // z transposed (N,D)
__device__ int           g_idx[NVEC];
__device__ unsigned int  g_hist[NCODE];
__device__ float         g_enorm[NCODE];
__device__ float         g_ehn2[NCODE];
__device__ float         g_eln2[NCODE];
__device__ float         g_Meh, g_Mel;
__device__ float4        g_top[NVEC];     // d1,d2,d3,margin
__device__ int4          g_topi[NVEC];    // i1,i2,i3,_
__device__ double        g_loss;

// ---------------- helpers --------------------------------------------------
__device__ __forceinline__ void mma_bf16(float c[4], uint32_t a0, uint32_t a1,
                                         uint32_t a2, uint32_t a3,
                                         uint32_t b0, uint32_t b1) {
    asm volatile(
        "mma.sync.aligned.m16n8k16.row.col.f32.bf16.bf16.f32 "
        "{%0,%1,%2,%3}, {%4,%5,%6,%7}, {%8,%9}, {%0,%1,%2,%3};"
        : "+f"(c[0]), "+f"(c[1]), "+f"(c[2]), "+f"(c[3])
        : "r"(a0), "r"(a1), "r"(a2), "r"(a3), "r"(b0), "r"(b1));
}
#define CP_ASYNC16(dst, src) \
    asm volatile("cp.async.cg.shared.global [%0], [%1], 16;" :: "r"(dst), "l"(src))
#define CP_COMMIT() asm volatile("cp.async.commit_group;" ::: "memory")
#define CP_WAIT1()  asm volatile("cp.async.wait_group 1;" ::: "memory")

__device__ __forceinline__ uint32_t smem_u32(const void* p) {
    uint32_t a;
    asm("{ .reg .u64 t; cvta.to.shared.u64 t, %1; cvt.u32.u64 %0, t; }" : "=r"(a) : "l"(p));
    return a;
}
__device__ __forceinline__ void ins3(float d, int c,
        float& d1, int& i1, float& d2, int& i2, float& d3, int& i3) {
    if (d < d3) {
        if (d < d2) {
            d3 = d2; i3 = i2;
            if (d < d1) { d2 = d1; i2 = i1; d1 = d; i1 = c; }
            else        { d2 = d;  i2 = c; }
        } else { d3 = d; i3 = c; }
    }
}

// ---------------- kernel 1: init + codebook prep ---------------------------
__global__ __launch_bounds__(256) void vq_embprep(const float* __restrict__ emb) {
    int c = blockIdx.x, d = threadIdx.x;
    if (d == 0) {
        g_hist[c] = 0u;
        if (c == 0) g_loss = 0.0;
    }
    float v = emb[(size_t)c * ZD + d];
    __nv_bfloat16 h = __float2bfloat16_rn(v);
    float hf = __bfloat162float(h);
    float lf = __bfloat162float(__float2bfloat16_rn(v - hf));
    g_eh[(size_t)c * ZD + d] = h;

    float sv = v * v, sh = hf * hf, sl = lf * lf;
    __shared__ float wv[8], wh[8], wl[8];
    int lane = d & 31, w = d >> 5;
    #pragma unroll
    for (int o = 16; o > 0; o >>= 1) {
        sv += __shfl_down_sync(0xffffffffu, sv, o);
        sh += __shfl_down_sync(0xffffffffu, sh, o);
        sl += __shfl_down_sync(0xffffffffu, sl, o);
    }
    if (lane == 0) { wv[w] = sv; wh[w] = sh; wl[w] = sl; }
    __syncthreads();
    if (d == 0) {
        float tv = 0.f, th = 0.f, tl = 0.f;
        #pragma unroll
        for (int i = 0; i < 8; i++) { tv += wv[i]; th += wh[i]; tl += wl[i]; }
        g_enorm[c] = tv;
        g_ehn2[c]  = th;
        g_eln2[c]  = tl;
    }
}

// ---------------- kernel 2: max code norms ---------------------------------
__global__ void vq_maxred() {
    __shared__ float mh[32], ml[32];
    int t = threadIdx.x, lane = t & 31, w = t >> 5;
    float a = g_ehn2[t], b = g_eln2[t];
    #pragma unroll
    for (int o = 16; o > 0; o >>= 1) {
        a = fmaxf(a, __shfl_down_sync(0xffffffffu, a, o));
        b = fmaxf(b, __shfl_down_sync(0xffffffffu, b, o));
    }
    if (lane == 0) { mh[w] = a; ml[w] = b; }
    __syncthreads();
    if (w == 0) {
        float x = mh[lane], y = ml[lane];
        #pragma unroll
        for (int o = 16; o > 0; o >>= 1) {
            x = fmaxf(x, __shfl_down_sync(0xffffffffu, x, o));
            y = fmaxf(y, __shfl_down_sync(0xffffffffu, y, o));
        }
        if (lane == 0) {
            g_Meh = sqrtf(x) * 1.001f;
            g_Mel = sqrtf(y) * 1.001f;
        }
    }
}

// ---------------- kernel 3: transpose z -> g_zt (N, D) ---------------------
__global__ __launch_bounds__(256) void vq_transpose(const float* __restrict__ z) {
    __shared__ float ts[32][33];
    int tid = threadIdx.x;
    int bt  = blockIdx.x & 127;         // t tile
    int rest = blockIdx.x >> 7;
    int d0  = (rest & 7) * 32;
    int b   = rest >> 3;
    int t0  = bt * 32;
    #pragma unroll
    for (int p = 0; p < 4; p++) {
        int dd = (tid >> 5) + p * 8;
        int tt = tid & 31;
        ts[dd][tt] = z[((size_t)(b * ZD + d0 + dd)) * ZT + t0 + tt];
    }
    __syncthreads();
    #pragma unroll
    for (int p = 0; p < 4; p++) {
        int tt = (tid >> 5) + p * 8;
        int dd = tid & 31;
        g_zt[((size_t)(b * ZT + t0 + tt)) * ZD + d0 + dd] = ts[dd][tt];
    }
}

// ---------------- kernel 4: 1-pass HMMA approx top-3 -----------------------
extern __shared__ char smem[];

__device__ __forceinline__ void prefetch_chunk(int it2, int tid) {
    int nt = it2 >> 3, kc = it2 & 7, buf = it2 & 1;
    #pragma unroll
    for (int q = 0; q < 2; q++) {
        int idx = tid + q * 256;            // 0..511
        int row = idx >> 2;
        int seg = idx & 3;
        const __nv_bfloat16* src =
            g_eh + ((size_t)(nt * TILE_N + row) * ZD + kc * BK + seg * 8);
        uint32_t dst = smem_u32(smem) + B_BASE + buf * B_HL + row * STRB_B + seg * 16;
        CP_ASYNC16(dst, src);
    }
}

__global__ __launch_bounds__(256, 1)
void vq_argmin_p1(const float* __restrict__ z) {
    int tid = threadIdx.x, lane = tid & 31, wid = tid >> 5;
    int g = lane >> 2, t4 = lane & 3;
    int wm = wid & 1, wn = wid >> 1;

    int n0 = blockIdx.x * TILE_M;
    int b  = n0 / ZT, t0 = n0 % ZT;
    const float* zb = z + (size_t)b * ZD * ZT + t0;

    float* sZh2 = (float*)(smem + SZH);
    float* sZl2 = (float*)(smem + SZL);
    if (tid < TILE_M) { sZh2[tid] = 0.f; sZl2[tid] = 0.f; }
    __syncthreads();

    // A tile: row r = tid&127 for every itl; accumulate per-row hi/lo norms
    float h2p = 0.f, l2p = 0.f;
    {
        int r = tid & 127;
        #pragma unroll 1
        for (int itl = 0; itl < 16; itl++) {
            int kq = (tid >> 7) + itl * 2;    // 8-dim group 0..31
            union { __nv_bfloat16 h[8]; uint4 u; } H;
            #pragma unroll
            for (int j = 0; j < 8; j++) {
                float v = zb[(size_t)(kq * 8 + j) * ZT + r];
                __nv_bfloat16 hh = __float2bfloat16_rn(v);
                float hf = __bfloat162float(hh);
                float lf = __bfloat162float(__float2bfloat16_rn(v - hf));
                H.h[j] = hh;
                h2p = fmaf(hf, hf, h2p);
                l2p = fmaf(lf, lf, l2p);
            }
            *(uint4*)(smem + A_H_OFF + (uint32_t)(r * STRA_B + kq * 16)) = H.u;
        }
        atomicAdd(&sZh2[r], h2p);
        atomicAdd(&sZl2[r], l2p);
    }

    prefetch_chunk(0, tid);
    CP_COMMIT();
    __syncthreads();

    float c[4][4][4];
    #pragma unroll
    for (int i = 0; i < 4; i++)
        #pragma unroll
        for (int j = 0; j < 4; j++)
            #pragma unroll
            for (int r = 0; r < 4; r++) c[i][j][r] = 0.f;

    // per-slot top-3: slots = (i 0..3) x (h 0..1)
    float td[4][2][3];
    int   ti[4][2][3];
    #pragma unroll
    for (int i = 0; i < 4; i++)
        #pragma unroll
        for (int h = 0; h < 2; h++)
            #pragma unroll
            for (int k = 0; k < 3; k++) { td[i][h][k] = 3.4e38f; ti[i][h][k] = 0; }

    #pragma unroll 1
    for (int it = 0; it < NITER; it++) {
        int nt = it >> 3, kc = it & 7;
        int buf = it & 1;
        if (it + 1 < NITER) prefetch_chunk(it + 1, tid);
        CP_COMMIT();
        CP_WAIT1();
        __syncthreads();

        const char* Bh = smem + B_BASE + buf * B_HL;

        #pragma unroll
        for (int ks = 0; ks < 2; ks++) {
            uint32_t kb = (uint32_t)(kc * BK + ks * 16);
            uint32_t ah[4][4], bh[4][2];
            #pragma unroll
            for (int i = 0; i < 4; i++) {
                int m0 = wm * 64 + i * 16 + g;
                const char* base = smem + A_H_OFF + m0 * STRA_B + (kb + 2 * t4) * 2;
                ah[i][0] = *(const uint32_t*)(base);
                ah[i][1] = *(const uint32_t*)(base + 8 * STRA_B);
                ah[i][2] = *(const uint32_t*)(base + 16);
                ah[i][3] = *(const uint32_t*)(base + 8 * STRA_B + 16);
            }
            #pragma unroll
            for (int j = 0; j < 4; j++) {
                int row = wn * 32 + j * 8 + g;
                const char* base = Bh + row * STRB_B + (ks * 16 + 2 * t4) * 2;
                bh[j][0] = *(const uint32_t*)(base);
                bh[j][1] = *(const uint32_t*)(base + 16);
            }
            #pragma unroll
            for (int i = 0; i < 4; i++)
                #pragma unroll
                for (int j = 0; j < 4; j++)
                    mma_bf16(c[i][j], ah[i][0], ah[i][1], ah[i][2], ah[i][3],
                             bh[j][0], bh[j][1]);
        }

        if (kc == KCH - 1) {
            #pragma unroll
            for (int j = 0; j < 4; j++) {
                int col0 = nt * TILE_N + wn * 32 + j * 8 + 2 * t4;
                float e0 = __ldg(&g_enorm[col0]);
                float e1 = __ldg(&g_enorm[col0 + 1]);
                #pragma unroll
                for (int i = 0; i < 4; i++) {
                    ins3(fmaf(-2.f, c[i][j][0], e0), col0,
                         td[i][0][0], ti[i][0][0], td[i][0][1], ti[i][0][1], td[i][0][2], ti[i][0][2]);
                    ins3(fmaf(-2.f, c[i][j][1], e1), col0 + 1,
                         td[i][0][0], ti[i][0][0], td[i][0][1], ti[i][0][1], td[i][0][2], ti[i][0][2]);
                    ins3(fmaf(-2.f, c[i][j][2], e0), col0,
                         td[i][1][0], ti[i][1][0], td[i][1][1], ti[i][1][1], td[i][1][2], ti[i][1][2]);
                    ins3(fmaf(-2.f, c[i][j][3], e1), col0 + 1,
                         td[i][1][0], ti[i][1][0], td[i][1][1], ti[i][1][1], td[i][1][2], ti[i][1][2]);
                    c[i][j][0] = c[i][j][1] = c[i][j][2] = c[i][j][3] = 0.f;
                }
            }
        }
        __syncthreads();
    }

    // quad (t4) reduce of top-3 triples
    #pragma unroll
    for (int i = 0; i < 4; i++)
        #pragma unroll
        for (int h = 0; h < 2; h++)
            #pragma unroll
            for (int sh = 1; sh <= 2; sh <<= 1) {
                #pragma unroll
                for (int k = 0; k < 3; k++) {
                    float od = __shfl_xor_sync(0xffffffffu, td[i][h][k], sh);
                    int   oc = __shfl_xor_sync(0xffffffffu, ti[i][h][k], sh);
                    ins3(od, oc, td[i][h][0], ti[i][h][0], td[i][h][1], ti[i][h][1],
                         td[i][h][2], ti[i][h][2]);
                }
            }

    float* stD = (float*)(smem + STD);
    int*   stI = (int*)(smem + STI);
    if (t4 == 0) {
        #pragma unroll
        for (int i = 0; i < 4; i++)
            #pragma unroll
            for (int h = 0; h < 2; h++) {
                int row = wm * 64 + i * 16 + g + h * 8;
                #pragma unroll
                for (int k = 0; k < 3; k++) {
                    stD[(row * 4 + wn) * 3 + k] = td[i][h][k];
                    stI[(row * 4 + wn) * 3 + k] = ti[i][h][k];
                }
            }
    }
    __syncthreads();
    if (tid < TILE_M) {
        float d1 = 3.4e38f, d2 = 3.4e38f, d3 = 3.4e38f;
        int   i1 = 0, i2 = 0, i3 = 0;
        #pragma unroll
        for (int w = 0; w < 4; w++)
            #pragma unroll
            for (int k = 0; k < 3; k++)
                ins3(stD[(tid * 4 + w) * 3 + k], stI[(tid * 4 + w) * 3 + k],
                     d1, i1, d2, i2, d3, i3);
        float zh = sqrtf(sZh2[tid]);
        float zl = sqrtf(sZl2[tid]);
        float Meh = g_Meh, Mel = g_Mel;
        float margin = 4.4f * (zh * Mel + zl * (Meh + Mel)) + 0.1f;
        g_top[n0 + tid]  = make_float4(d1, d2, d3, margin);
        g_topi[n0 + tid] = make_int4(i1, i2, i3, 0);
    }
}

// ---------------- kernel 5: exact resolve ----------------------------------
__global__ __launch_bounds__(256)
void vq_resolve(const float* __restrict__ emb) {
    int lane = threadIdx.x & 31, wid = threadIdx.x >> 5;
    int row = blockIdx.x * 8 + wid;

    float4 t = g_top[row];
    int4   ix = g_topi[row];
    int idx;
    if (t.y - t.x > t.w) {
        idx = ix.x;                               // unambiguous
    } else {
        float4 za = *(const float4*)(g_zt + (size_t)row * ZD + lane * 8);
        float4 zb = *(const float4*)(g_zt + (size_t)row * ZD + lane * 8 + 4);
        // exact (fp32) distance sans ||z||^2
        auto edist = [&](int cc) -> float {
            const float4* e4 = (const float4*)(emb + (size_t)cc * ZD + lane * 8);
            float4 ea = e4[0], eb = e4[1];
            float s = za.x * ea.x + za.y * ea.y + za.z * ea.z + za.w * ea.w
                    + zb.x * eb.x + zb.y * eb.y + zb.z * eb.z + zb.w * eb.w;
            #pragma unroll
            for (int o = 16; o > 0; o >>= 1) s += __shfl_xor_sync(0xffffffffu, s, o);
            return fmaf(-2.f, s, __ldg(&g_enorm[cc]));
        };
        if (t.z - t.x > t.w) {
            // true argmin is in {i1, i2}
            int ca = ix.x < ix.y ? ix.x : ix.y;
            int cb = ix.x < ix.y ? ix.y : ix.x;
            float da = edist(ca), db = edist(cb);
            idx = (db < da) ? cb : ca;            // tie -> lower index (ca)
        } else {
            // full exact scan
            float bd = 3.4e38f; int bi = 0;
            for (int cc = 0; cc < NCODE; cc++) {
                float d = edist(cc);
                if (d < bd) { bd = d; bi = cc; }
            }
            idx = bi;
        }
    }
    if (lane == 0) {
        g_idx[row] = idx;
        atomicAdd(&g_hist[idx], 1u);
    }
}

// ---------------- kernel 6: coalesced gather + output + loss ---------------
__global__ __launch_bounds__(256)
void vq_gather_kernel(const float* __restrict__ z, const float* __restrict__ emb,
                      float* __restrict__ out) {
    __shared__ int   sidx[32];
    __shared__ float sE[32][257];
    int tid = threadIdx.x;
    int b   = blockIdx.x >> 7;
    int t0  = (blockIdx.x & 127) * 32;

    if (tid < 32) sidx[tid] = g_idx[b * ZT + t0 + tid];
    __syncthreads();

    {
        int r = tid >> 3;
        const float* row = emb + (size_t)sidx[r] * ZD;
        #pragma unroll
        for (int q = 0; q < 8; q++) {
            int c4 = (tid & 7) + q * 8;
            float4 v = *(const float4*)(row + c4 * 4);
            sE[r][c4 * 4 + 0] = v.x;
            sE[r][c4 * 4 + 1] = v.y;
            sE[r][c4 * 4 + 2] = v.z;
            sE[r][c4 * 4 + 3] = v.w;
        }
    }
    __syncthreads();

    float lsum = 0.f;
    int w = tid >> 5, lane = tid & 31;
    #pragma unroll 4
    for (int d = w; d < ZD; d += 8) {
        float e = sE[lane][d];
        size_t off = ((size_t)(b * ZD + d)) * ZT + t0 + lane;
        float zv = z[off];
        out[off] = e;
        float df = zv - e;
        lsum = fmaf(df, df, lsum);
    }

    __shared__ float ws[8];
    #pragma unroll
    for (int o = 16; o > 0; o >>= 1) lsum += __shfl_down_sync(0xffffffffu, lsum, o);
    if (lane == 0) ws[w] = lsum;
    __syncthreads();
    if (w == 0) {
        float s = (lane < 8) ? ws[lane] : 0.f;
        #pragma unroll
        for (int o = 4; o > 0; o >>= 1) s += __shfl_down_sync(0xffffffffu, s, o);
        if (lane == 0) atomicAdd(&g_loss, (double)s);
    }
}

// ---------------- kernel 7: perplexity + scalar outputs --------------------
__global__ void vq_finalize_kernel(float* __restrict__ out, int out_size) {
    __shared__ float warpsum[32];
    int t = threadIdx.x;
    float p = (float)g_hist[t] / (float)NVEC;
    float term = p * logf(p + 1e-10f);
    int lane = t & 31, w = t >> 5;
    #pragma unroll
    for (int o = 16; o > 0; o >>= 1) term += __shfl_down_sync(0xffffffffu, term, o);
    if (lane == 0) warpsum[w] = term;
    __syncthreads();
    if (w == 0) {
        float s = warpsum[lane];
        #pragma unroll
        for (int o = 16; o > 0; o >>= 1) s += __shfl_down_sync(0xffffffffu, s, o);
        if (lane == 0) {
            float perp = expf(-s);
            float loss = (float)g_loss;
            out[out_size - 3] = loss;
            out[out_size - 2] = loss;
            out[out_size - 1] = perp;
        }
    }
}

// ---------------- launcher -------------------------------------------------
extern "C" void kernel_launch(void* const* d_in, const int* in_sizes, int n_in,
                              void* d_out, int out_size) {
    const float* z   = (const float*)d_in[0];
    const float* emb = (const float*)d_in[1];
    if (n_in >= 2 && in_sizes[0] == NCODE * ZD && in_sizes[1] == NELEM) {
        const float* tmp = z; z = emb; emb = tmp;
    }
    float* out = (float*)d_out;

    cudaFuncSetAttribute(vq_argmin_p1,
                         cudaFuncAttributeMaxDynamicSharedMemorySize, SMEM_TOTAL);

    vq_embprep<<<NCODE, 256>>>(emb);
    vq_maxred<<<1, 1024>>>();
    vq_transpose<<<16384, 256>>>(z);
    vq_argmin_p1<<<NVEC / TILE_M, 256, SMEM_TOTAL>>>(z);
    vq_resolve<<<NVEC / 8, 256>>>(emb);
    vq_gather_kernel<<<ZB * (ZT / 32), 256>>>(z, emb, out);
    vq_finalize_kernel<<<1, 1024>>>(out, out_size);
}

// round 11
// speedup vs baseline: 1.5800x; 1.5800x over previous
#include <cuda_runtime.h>
#include <cuda_bf16.h>
#include <stdint.h>
#include <math.h>

#define ZB   16
#define ZD   256
#define ZT   4096
#define NVEC (ZB*ZT)            // 65536
#define NELEM (ZB*ZD*ZT)        // 16777216
#define NCODE 1024

#define TILE_M 64
#define TILE_N 128
#define BK     32
#define NT_TILES (NCODE/TILE_N)   // 8
#define KCH      (ZD/BK)          // 8
#define NITER    (NT_TILES*KCH)   // 64
#define THREADS  256

// A (hi only): row stride 264 bf16 = 528 B
#define STRA_B 528
#define A_H_OFF 0
#define B_BASE (TILE_M*STRA_B)             // 33792
// B chunk: 128 rows x 80B, hi+lo, double buffered
#define STRB_B 80
#define B_HL   (TILE_N*STRB_B)             // 10240
#define B_BUF  (2*B_HL)                    // 20480
#define SMEM_TOTAL (B_BASE + 2*B_BUF)      // 74752
// epilogue scratch overlaps B region (B dead by then)
#define STD    B_BASE                      // [row][wn][3] float
#define STI    (B_BASE + TILE_M*4*3*4)     // +3072

// ---------------- scratch --------------------------------------------------
__device__ __align__(16) __nv_bfloat16 g_eh[NCODE*ZD];
__device__ __align__(16) __nv_bfloat16 g_el[NCODE*ZD];
__device__ int           g_idx[NVEC];
__device__ unsigned int  g_hist[NCODE];
__device__ float         g_enorm[NCODE];
__device__ float         g_Me;            // max ||e||
__device__ float4        g_top[NVEC];     // d1,d2,d3,margin
__device__ int4          g_topi[NVEC];
__device__ double        g_loss;

// ---------------- helpers --------------------------------------------------
__device__ __forceinline__ void mma_bf16(float c[4], uint32_t a0, uint32_t a1,
                                         uint32_t a2, uint32_t a3,
                                         uint32_t b0, uint32_t b1) {
    asm volatile(
        "mma.sync.aligned.m16n8k16.row.col.f32.bf16.bf16.f32 "
        "{%0,%1,%2,%3}, {%4,%5,%6,%7}, {%8,%9}, {%0,%1,%2,%3};"
        : "+f"(c[0]), "+f"(c[1]), "+f"(c[2]), "+f"(c[3])
        : "r"(a0), "r"(a1), "r"(a2), "r"(a3), "r"(b0), "r"(b1));
}
#define CP_ASYNC16(dst, src) \
    asm volatile("cp.async.cg.shared.global [%0], [%1], 16;" :: "r"(dst), "l"(src))
#define CP_COMMIT() asm volatile("cp.async.commit_group;" ::: "memory")
#define CP_WAIT1()  asm volatile("cp.async.wait_group 1;" ::: "memory")

__device__ __forceinline__ uint32_t smem_u32(const void* p) {
    uint32_t a;
    asm("{ .reg .u64 t; cvta.to.shared.u64 t, %1; cvt.u32.u64 %0, t; }" : "=r"(a) : "l"(p));
    return a;
}
__device__ __forceinline__ void ins3(float d, int c,
        float& d1, int& i1, float& d2, int& i2, float& d3, int& i3) {
    if (d < d3) {
        if (d < d2) {
            d3 = d2; i3 = i2;
            if (d < d1) { d2 = d1; i2 = i1; d1 = d; i1 = c; }
            else        { d2 = d;  i2 = c; }
        } else { d3 = d; i3 = c; }
    }
}

// ---------------- kernel 1: init + codebook prep ---------------------------
__global__ __launch_bounds__(256) void vq_embprep(const float* __restrict__ emb) {
    int c = blockIdx.x, d = threadIdx.x;
    if (d == 0) {
        g_hist[c] = 0u;
        if (c == 0) g_loss = 0.0;
    }
    float v = emb[(size_t)c * ZD + d];
    __nv_bfloat16 h = __float2bfloat16_rn(v);
    float hf = __bfloat162float(h);
    g_eh[(size_t)c * ZD + d] = h;
    g_el[(size_t)c * ZD + d] = __float2bfloat16_rn(v - hf);

    float sv = v * v;
    __shared__ float wv[8];
    int lane = d & 31, w = d >> 5;
    #pragma unroll
    for (int o = 16; o > 0; o >>= 1) sv += __shfl_down_sync(0xffffffffu, sv, o);
    if (lane == 0) wv[w] = sv;
    __syncthreads();
    if (d == 0) {
        float tv = 0.f;
        #pragma unroll
        for (int i = 0; i < 8; i++) tv += wv[i];
        g_enorm[c] = tv;
    }
}

// ---------------- kernel 2: max ||e|| --------------------------------------
__global__ void vq_maxred() {
    __shared__ float mh[32];
    int t = threadIdx.x, lane = t & 31, w = t >> 5;
    float a = g_enorm[t];
    #pragma unroll
    for (int o = 16; o > 0; o >>= 1) a = fmaxf(a, __shfl_down_sync(0xffffffffu, a, o));
    if (lane == 0) mh[w] = a;
    __syncthreads();
    if (w == 0) {
        float x = mh[lane];
        #pragma unroll
        for (int o = 16; o > 0; o >>= 1) x = fmaxf(x, __shfl_down_sync(0xffffffffu, x, o));
        if (lane == 0) g_Me = sqrtf(x) * 1.001f;
    }
}

// ---------------- kernel 3: 2-pass HMMA approx top-3 -----------------------
extern __shared__ char smem[];

__device__ __forceinline__ void prefetch_chunk(int it2, int tid) {
    int nt = it2 >> 3, kc = it2 & 7, buf = it2 & 1;
    #pragma unroll
    for (int q = 0; q < 4; q++) {
        int idx = tid + q * THREADS;        // 0..1023
        int hl  = idx >> 9;
        int rem = idx & 511;
        int row = rem >> 2;
        int seg = rem & 3;
        const __nv_bfloat16* src =
            (hl ? g_el : g_eh) + ((size_t)(nt * TILE_N + row) * ZD + kc * BK + seg * 8);
        uint32_t dst = smem_u32(smem) + B_BASE + buf * B_BUF + hl * B_HL
                     + row * STRB_B + seg * 16;
        CP_ASYNC16(dst, src);
    }
}

__global__ __launch_bounds__(THREADS, 2)
void vq_argmin_p2(const float* __restrict__ z) {
    __shared__ float sZl2[TILE_M];
    int tid = threadIdx.x, lane = tid & 31, wid = tid >> 5;
    int g = lane >> 2, t4 = lane & 3;
    int wm = wid & 1, wn = wid >> 1;

    int n0 = blockIdx.x * TILE_M;
    int b  = n0 / ZT, t0 = n0 % ZT;
    const float* zb = z + (size_t)b * ZD * ZT + t0;

    if (tid < TILE_M) sZl2[tid] = 0.f;
    __syncthreads();

    // A tile (hi) + per-row ||zl||^2  (64 rows x 256 dims)
    {
        int r = tid & 63;
        float l2p = 0.f;
        #pragma unroll 1
        for (int itl = 0; itl < 8; itl++) {
            int kq = (tid >> 6) + itl * 4;       // 0..31
            union { __nv_bfloat16 h[8]; uint4 u; } H;
            #pragma unroll
            for (int j = 0; j < 8; j++) {
                float v = zb[(size_t)(kq * 8 + j) * ZT + r];
                __nv_bfloat16 hh = __float2bfloat16_rn(v);
                float lf = __bfloat162float(__float2bfloat16_rn(v - __bfloat162float(hh)));
                H.h[j] = hh;
                l2p = fmaf(lf, lf, l2p);
            }
            *(uint4*)(smem + A_H_OFF + (uint32_t)(r * STRA_B + kq * 16)) = H.u;
        }
        atomicAdd(&sZl2[r], l2p);
    }

    prefetch_chunk(0, tid);
    CP_COMMIT();
    __syncthreads();

    float c[2][4][4];
    #pragma unroll
    for (int i = 0; i < 2; i++)
        #pragma unroll
        for (int j = 0; j < 4; j++)
            #pragma unroll
            for (int r = 0; r < 4; r++) c[i][j][r] = 0.f;

    float td[2][2][3];
    int   ti[2][2][3];
    #pragma unroll
    for (int i = 0; i < 2; i++)
        #pragma unroll
        for (int h = 0; h < 2; h++)
            #pragma unroll
            for (int k = 0; k < 3; k++) { td[i][h][k] = 3.4e38f; ti[i][h][k] = 0; }

    #pragma unroll 1
    for (int it = 0; it < NITER; it++) {
        int nt = it >> 3, kc = it & 7;
        int buf = it & 1;
        if (it + 1 < NITER) prefetch_chunk(it + 1, tid);
        CP_COMMIT();
        CP_WAIT1();
        __syncthreads();

        const char* Bh = smem + B_BASE + buf * B_BUF;
        const char* Bl = Bh + B_HL;

        #pragma unroll
        for (int ks = 0; ks < 2; ks++) {
            uint32_t kb = (uint32_t)(kc * BK + ks * 16);
            uint32_t ah[2][4], bh[4][2], bl[4][2];
            #pragma unroll
            for (int i = 0; i < 2; i++) {
                int m0 = wm * 32 + i * 16 + g;
                const char* base = smem + A_H_OFF + m0 * STRA_B + (kb + 2 * t4) * 2;
                ah[i][0] = *(const uint32_t*)(base);
                ah[i][1] = *(const uint32_t*)(base + 8 * STRA_B);
                ah[i][2] = *(const uint32_t*)(base + 16);
                ah[i][3] = *(const uint32_t*)(base + 8 * STRA_B + 16);
            }
            #pragma unroll
            for (int j = 0; j < 4; j++) {
                int row = wn * 32 + j * 8 + g;
                const char* base = Bh + row * STRB_B + (ks * 16 + 2 * t4) * 2;
                bh[j][0] = *(const uint32_t*)(base);
                bh[j][1] = *(const uint32_t*)(base + 16);
            }
            #pragma unroll
            for (int i = 0; i < 2; i++)
                #pragma unroll
                for (int j = 0; j < 4; j++)
                    mma_bf16(c[i][j], ah[i][0], ah[i][1], ah[i][2], ah[i][3],
                             bh[j][0], bh[j][1]);
            #pragma unroll
            for (int j = 0; j < 4; j++) {
                int row = wn * 32 + j * 8 + g;
                const char* base = Bl + row * STRB_B + (ks * 16 + 2 * t4) * 2;
                bl[j][0] = *(const uint32_t*)(base);
                bl[j][1] = *(const uint32_t*)(base + 16);
            }
            #pragma unroll
            for (int i = 0; i < 2; i++)
                #pragma unroll
                for (int j = 0; j < 4; j++)
                    mma_bf16(c[i][j], ah[i][0], ah[i][1], ah[i][2], ah[i][3],
                             bl[j][0], bl[j][1]);
        }

        if (kc == KCH - 1) {
            #pragma unroll
            for (int j = 0; j < 4; j++) {
                int col0 = nt * TILE_N + wn * 32 + j * 8 + 2 * t4;
                float e0 = __ldg(&g_enorm[col0]);
                float e1 = __ldg(&g_enorm[col0 + 1]);
                #pragma unroll
                for (int i = 0; i < 2; i++) {
                    ins3(fmaf(-2.f, c[i][j][0], e0), col0,
                         td[i][0][0], ti[i][0][0], td[i][0][1], ti[i][0][1], td[i][0][2], ti[i][0][2]);
                    ins3(fmaf(-2.f, c[i][j][1], e1), col0 + 1,
                         td[i][0][0], ti[i][0][0], td[i][0][1], ti[i][0][1], td[i][0][2], ti[i][0][2]);
                    ins3(fmaf(-2.f, c[i][j][2], e0), col0,
                         td[i][1][0], ti[i][1][0], td[i][1][1], ti[i][1][1], td[i][1][2], ti[i][1][2]);
                    ins3(fmaf(-2.f, c[i][j][3], e1), col0 + 1,
                         td[i][1][0], ti[i][1][0], td[i][1][1], ti[i][1][1], td[i][1][2], ti[i][1][2]);
                    c[i][j][0] = c[i][j][1] = c[i][j][2] = c[i][j][3] = 0.f;
                }
            }
        }
        __syncthreads();
    }

    // quad (t4) merge
    #pragma unroll
    for (int i = 0; i < 2; i++)
        #pragma unroll
        for (int h = 0; h < 2; h++)
            #pragma unroll
            for (int sh = 1; sh <= 2; sh <<= 1)
                #pragma unroll
                for (int k = 0; k < 3; k++) {
                    float od = __shfl_xor_sync(0xffffffffu, td[i][h][k], sh);
                    int   oc = __shfl_xor_sync(0xffffffffu, ti[i][h][k], sh);
                    ins3(od, oc, td[i][h][0], ti[i][h][0], td[i][h][1], ti[i][h][1],
                         td[i][h][2], ti[i][h][2]);
                }

    float* stD = (float*)(smem + STD);
    int*   stI = (int*)(smem + STI);
    if (t4 == 0) {
        #pragma unroll
        for (int i = 0; i < 2; i++)
            #pragma unroll
            for (int h = 0; h < 2; h++) {
                int row = wm * 32 + i * 16 + h * 8 + g;   // 0..63
                #pragma unroll
                for (int k = 0; k < 3; k++) {
                    stD[(row * 4 + wn) * 3 + k] = td[i][h][k];
                    stI[(row * 4 + wn) * 3 + k] = ti[i][h][k];
                }
            }
    }
    __syncthreads();
    if (tid < TILE_M) {
        float d1 = 3.4e38f, d2 = 3.4e38f, d3 = 3.4e38f;
        int   i1 = 0, i2 = 0, i3 = 0;
        #pragma unroll
        for (int w = 0; w < 4; w++)
            #pragma unroll
            for (int k = 0; k < 3; k++)
                ins3(stD[(tid * 4 + w) * 3 + k], stI[(tid * 4 + w) * 3 + k],
                     d1, i1, d2, i2, d3, i3);
        float zl = sqrtf(sZl2[tid]);
        // each approx distance carries error <= 2*||zl||*||e||; comparing two
        // approx values needs the SUM of both bounds: 4*zl*Me (+rounding pad).
        float margin = 4.3f * zl * g_Me + 0.25f;
        g_top[n0 + tid]  = make_float4(d1, d2, d3, margin);
        g_topi[n0 + tid] = make_int4(i1, i2, i3, 0);
    }
}

// ---------------- kernel 4: exact resolve ----------------------------------
__global__ __launch_bounds__(256)
void vq_resolve(const float* __restrict__ z, const float* __restrict__ emb) {
    int lane = threadIdx.x & 31, wid = threadIdx.x >> 5;
    int row = blockIdx.x * 8 + wid;

    float4 t = g_top[row];
    int4   ix = g_topi[row];
    int idx;
    if (t.y - t.x > t.w) {
        idx = ix.x;
    } else {
        int b = row / ZT, tt = row % ZT;
        const float* zp = z + (size_t)b * ZD * ZT + tt;
        float zr[8];
        #pragma unroll
        for (int j = 0; j < 8; j++) zr[j] = zp[(size_t)(lane * 8 + j) * ZT];
        auto edist = [&](int cc) -> float {
            const float4* e4 = (const float4*)(emb + (size_t)cc * ZD + lane * 8);
            float4 ea = e4[0], eb = e4[1];
            float s = zr[0] * ea.x + zr[1] * ea.y + zr[2] * ea.z + zr[3] * ea.w
                    + zr[4] * eb.x + zr[5] * eb.y + zr[6] * eb.z + zr[7] * eb.w;
            #pragma unroll
            for (int o = 16; o > 0; o >>= 1) s += __shfl_xor_sync(0xffffffffu, s, o);
            return fmaf(-2.f, s, __ldg(&g_enorm[cc]));
        };
        if (t.z - t.x > t.w) {
            int ca = ix.x < ix.y ? ix.x : ix.y;
            int cb = ix.x < ix.y ? ix.y : ix.x;
            float da = edist(ca), db = edist(cb);
            idx = (db < da) ? cb : ca;
        } else {
            float bd = 3.4e38f; int bi = 0;
            for (int cc = 0; cc < NCODE; cc++) {
                float d = edist(cc);
                if (d < bd) { bd = d; bi = cc; }
            }
            idx = bi;
        }
    }
    if (lane == 0) {
        g_idx[row] = idx;
        atomicAdd(&g_hist[idx], 1u);
    }
}

// ---------------- kernel 5: coalesced gather + output + loss ---------------
__global__ __launch_bounds__(256)
void vq_gather_kernel(const float* __restrict__ z, const float* __restrict__ emb,
                      float* __restrict__ out) {
    __shared__ int   sidx[32];
    __shared__ float sE[32][257];
    int tid = threadIdx.x;
    int b   = blockIdx.x >> 7;
    int t0  = (blockIdx.x & 127) * 32;

    if (tid < 32) sidx[tid] = g_idx[b * ZT + t0 + tid];
    __syncthreads();

    {
        int r = tid >> 3;
        const float* row = emb + (size_t)sidx[r] * ZD;
        #pragma unroll
        for (int q = 0; q < 8; q++) {
            int c4 = (tid & 7) + q * 8;
            float4 v = *(const float4*)(row + c4 * 4);
            sE[r][c4 * 4 + 0] = v.x;
            sE[r][c4 * 4 + 1] = v.y;
            sE[r][c4 * 4 + 2] = v.z;
            sE[r][c4 * 4 + 3] = v.w;
        }
    }
    __syncthreads();

    float lsum = 0.f;
    int w = tid >> 5, lane = tid & 31;
    #pragma unroll 4
    for (int d = w; d < ZD; d += 8) {
        float e = sE[lane][d];
        size_t off = ((size_t)(b * ZD + d)) * ZT + t0 + lane;
        float zv = z[off];
        out[off] = e;
        float df = zv - e;
        lsum = fmaf(df, df, lsum);
    }

    __shared__ float ws[8];
    #pragma unroll
    for (int o = 16; o > 0; o >>= 1) lsum += __shfl_down_sync(0xffffffffu, lsum, o);
    if (lane == 0) ws[w] = lsum;
    __syncthreads();
    if (w == 0) {
        float s = (lane < 8) ? ws[lane] : 0.f;
        #pragma unroll
        for (int o = 4; o > 0; o >>= 1) s += __shfl_down_sync(0xffffffffu, s, o);
        if (lane == 0) atomicAdd(&g_loss, (double)s);
    }
}

// ---------------- kernel 6: perplexity + scalar outputs --------------------
__global__ void vq_finalize_kernel(float* __restrict__ out, int out_size) {
    __shared__ float warpsum[32];
    int t = threadIdx.x;
    float p = (float)g_hist[t] / (float)NVEC;
    float term = p * logf(p + 1e-10f);
    int lane = t & 31, w = t >> 5;
    #pragma unroll
    for (int o = 16; o > 0; o >>= 1) term += __shfl_down_sync(0xffffffffu, term, o);
    if (lane == 0) warpsum[w] = term;
    __syncthreads();
    if (w == 0) {
        float s = warpsum[lane];
        #pragma unroll
        for (int o = 16; o > 0; o >>= 1) s += __shfl_down_sync(0xffffffffu, s, o);
        if (lane == 0) {
            float perp = expf(-s);
            float loss = (float)g_loss;
            out[out_size - 3] = loss;
            out[out_size - 2] = loss;
            out[out_size - 1] = perp;
        }
    }
}

// ---------------- launcher -------------------------------------------------
extern "C" void kernel_launch(void* const* d_in, const int* in_sizes, int n_in,
                              void* d_out, int out_size) {
    const float* z   = (const float*)d_in[0];
    const float* emb = (const float*)d_in[1];
    if (n_in >= 2 && in_sizes[0] == NCODE * ZD && in_sizes[1] == NELEM) {
        const float* tmp = z; z = emb; emb = tmp;
    }
    float* out = (float*)d_out;

    cudaFuncSetAttribute(vq_argmin_p2,
                         cudaFuncAttributeMaxDynamicSharedMemorySize, SMEM_TOTAL);

    vq_embprep<<<NCODE, 256>>>(emb);
    vq_maxred<<<1, 1024>>>();
    vq_argmin_p2<<<NVEC / TILE_M, THREADS, SMEM_TOTAL>>>(z);
    vq_resolve<<<NVEC / 8, 256>>>(z, emb);
    vq_gather_kernel<<<ZB * (ZT / 32), 256>>>(z, emb, out);
    vq_finalize_kernel<<<1, 1024>>>(out, out_size);
}